// round 1
// baseline (speedup 1.0000x reference)
#include <cuda_runtime.h>
#include <cstdint>
#include <cstddef>

#define N_USERS   100000
#define N_NODES   500000
#define DIM       64
#define N_EDGES   2000000
#define BATCH     4096

// -------- device scratch (static, allocation-free) --------
__device__ float    g_XA[(size_t)N_NODES * DIM];   // 128 MB
__device__ float    g_XB[(size_t)N_NODES * DIM];   // 128 MB
__device__ float    g_dinv[N_NODES];
__device__ unsigned g_deg[N_NODES];
__device__ float    g_norm[N_EDGES];
__device__ float    g_acc[(size_t)3 * BATCH * DIM]; // batch accumulators: [user|pos|neg] rows

// -------- helpers --------
__global__ void k_zero_deg() {
    int i = blockIdx.x * blockDim.x + threadIdx.x;
    if (i < N_NODES) g_deg[i] = 0u;
}

__global__ void k_deg(const int* __restrict__ dst) {
    int e = blockIdx.x * blockDim.x + threadIdx.x;
    if (e < N_EDGES) atomicAdd(&g_deg[dst[e]], 1u);
}

__global__ void k_dinv() {
    int i = blockIdx.x * blockDim.x + threadIdx.x;
    if (i < N_NODES) {
        unsigned d = g_deg[i];
        g_dinv[i] = d ? rsqrtf((float)d) : 0.0f;
    }
}

__global__ void k_norm(const int* __restrict__ src, const int* __restrict__ dst) {
    int e = blockIdx.x * blockDim.x + threadIdx.x;
    if (e < N_EDGES) g_norm[e] = g_dinv[src[e]] * g_dinv[dst[e]];
}

// zero one of the 128MB node buffers (float4 stores)
__global__ void k_zero_nodes(int sel) {
    float4* p = (float4*)(sel == 1 ? g_XA : g_XB);
    size_t i = (size_t)blockIdx.x * blockDim.x + threadIdx.x;
    if (i < (size_t)N_NODES * (DIM / 4))
        p[i] = make_float4(0.f, 0.f, 0.f, 0.f);
}

// init batch accumulators with ego (layer-0) embeddings
__global__ void k_init_acc(const float* __restrict__ emb,
                           const int* __restrict__ u,
                           const int* __restrict__ p,
                           const int* __restrict__ n) {
    int t = blockIdx.x * blockDim.x + threadIdx.x;
    if (t >= 3 * BATCH * (DIM / 4)) return;
    int row = t >> 4, c = t & 15;
    int idx = (row < BATCH) ? u[row]
            : (row < 2 * BATCH) ? p[row - BATCH]
                                : n[row - 2 * BATCH];
    ((float4*)g_acc)[t] = __ldg((const float4*)emb + (size_t)idx * 16 + c);
}

// acc += X[idx] for all batch rows, after each layer
__global__ void k_gather_add(int xsel,
                             const int* __restrict__ u,
                             const int* __restrict__ p,
                             const int* __restrict__ n) {
    int t = blockIdx.x * blockDim.x + threadIdx.x;
    if (t >= 3 * BATCH * (DIM / 4)) return;
    int row = t >> 4, c = t & 15;
    int idx = (row < BATCH) ? u[row]
            : (row < 2 * BATCH) ? p[row - BATCH]
                                : n[row - 2 * BATCH];
    const float* x = (xsel == 1) ? g_XA : g_XB;
    float4 v = __ldg((const float4*)x + (size_t)idx * 16 + c);
    float4* a = (float4*)g_acc + t;
    float4 av = *a;
    av.x += v.x; av.y += v.y; av.z += v.z; av.w += v.w;
    *a = av;
}

// one propagation layer: y[dst] += x[src] * norm[e]
// 16 threads per edge, float4 gather + red.global.add.v4.f32 scatter
__global__ void k_prop(const float* __restrict__ emb, int xsel, int ysel,
                       const int* __restrict__ src, const int* __restrict__ dst) {
    unsigned gid = blockIdx.x * blockDim.x + threadIdx.x;
    unsigned e = gid >> 4;
    if (e >= N_EDGES) return;
    int lane = gid & 15;

    const float* x = (xsel == 0) ? emb : (xsel == 1 ? g_XA : g_XB);
    float*       y = (ysel == 1) ? g_XA : g_XB;

    int   s = __ldg(src + e);
    int   d = __ldg(dst + e);
    float w = __ldg(g_norm + e);

    float4 v = __ldg((const float4*)x + (size_t)s * 16 + lane);
    float4* a = (float4*)y + (size_t)d * 16 + lane;
    asm volatile("red.global.add.v4.f32 [%0], {%1, %2, %3, %4};"
                 :: "l"(a), "f"(v.x * w), "f"(v.y * w), "f"(v.z * w), "f"(v.w * w)
                 : "memory");
}

__global__ void k_zero_out(float* out) {
    if (threadIdx.x == 0 && blockIdx.x == 0) out[0] = 0.0f;
}

// final BPR + L2 loss. One warp per batch element, 2 dims per lane.
__global__ void k_loss(const float* __restrict__ emb,
                       const int* __restrict__ user,
                       const int* __restrict__ pos,
                       const int* __restrict__ neg,
                       float* __restrict__ out) {
    int w = (blockIdx.x * blockDim.x + threadIdx.x) >> 5;
    int lane = threadIdx.x & 31;
    if (w >= BATCH) return;

    const float* U  = g_acc + (size_t)w * DIM;
    const float* P  = g_acc + (size_t)(BATCH + w) * DIM;
    const float* Nn = g_acc + (size_t)(2 * BATCH + w) * DIM;

    int ui = user[w], pi = pos[w], ni = neg[w];

    float pd = 0.f, nd = 0.f, sq = 0.f;
#pragma unroll
    for (int k = 0; k < 2; k++) {
        int j = lane + 32 * k;
        float uu = U[j], pp = P[j], nn = Nn[j];
        pd += uu * pp;
        nd += uu * nn;
        float a = __ldg(emb + (size_t)ui * DIM + j);
        float b = __ldg(emb + (size_t)pi * DIM + j);
        float c = __ldg(emb + (size_t)ni * DIM + j);
        sq += a * a + b * b + c * c;
    }
#pragma unroll
    for (int o = 16; o; o >>= 1) {
        pd += __shfl_xor_sync(0xffffffffu, pd, o);
        nd += __shfl_xor_sync(0xffffffffu, nd, o);
        sq += __shfl_xor_sync(0xffffffffu, sq, o);
    }
    if (lane == 0) {
        // acc rows are sums over 4 stacked layers; mean divides each by 4 -> dot scales 1/16
        float z = (nd - pd) * 0.0625f;
        float sp = fmaxf(z, 0.f) + log1pf(expf(-fabsf(z)));       // softplus(neg - pos)
        // total = ( sum_b softplus + L2_REG*0.5*sum_b sq ) / BATCH
        atomicAdd(out, (sp + 5e-5f * sq) * (1.0f / BATCH));
    }
}

extern "C" void kernel_launch(void* const* d_in, const int* in_sizes, int n_in,
                              void* d_out, int out_size) {
    const float* emb  = (const float*)d_in[0];
    const int*   edge = (const int*)d_in[1];
    const int*   src  = edge;
    const int*   dst  = edge + N_EDGES;
    const int*   user = (const int*)d_in[2];
    const int*   pos  = (const int*)d_in[3];
    const int*   neg  = (const int*)d_in[4];
    float*       out  = (float*)d_out;

    const int T = 256;
    const int G_NODES = (N_NODES + T - 1) / T;
    const int G_EDGES = (N_EDGES + T - 1) / T;
    const int G_ZERO  = (int)(((size_t)N_NODES * (DIM / 4) + T - 1) / T);   // 31250
    const int G_PROP  = (int)(((size_t)N_EDGES * 16 + T - 1) / T);          // 125000
    const int G_ACC   = (3 * BATCH * (DIM / 4) + T - 1) / T;                // 768

    // degree -> dinv -> per-edge norm
    k_zero_deg<<<G_NODES, T>>>();
    k_deg<<<G_EDGES, T>>>(dst);
    k_dinv<<<G_NODES, T>>>();
    k_norm<<<G_EDGES, T>>>(src, dst);

    // layer-0 term of the stacked mean
    k_init_acc<<<G_ACC, T>>>(emb, user, pos, neg);

    // layer 1: emb -> XA
    k_zero_nodes<<<G_ZERO, T>>>(1);
    k_prop<<<G_PROP, T>>>(emb, 0, 1, src, dst);
    k_gather_add<<<G_ACC, T>>>(1, user, pos, neg);

    // layer 2: XA -> XB
    k_zero_nodes<<<G_ZERO, T>>>(2);
    k_prop<<<G_PROP, T>>>(emb, 1, 2, src, dst);
    k_gather_add<<<G_ACC, T>>>(2, user, pos, neg);

    // layer 3: XB -> XA
    k_zero_nodes<<<G_ZERO, T>>>(1);
    k_prop<<<G_PROP, T>>>(emb, 2, 1, src, dst);
    k_gather_add<<<G_ACC, T>>>(1, user, pos, neg);

    // loss
    k_zero_out<<<1, 1>>>(out);
    k_loss<<<BATCH / 8, T>>>(emb, user, pos, neg, out);
}